// round 10
// baseline (speedup 1.0000x reference)
#include <cuda_runtime.h>
#include <math.h>
#include <stdint.h>
#include <stddef.h>

// ---------------------------------------------------------------------------
// Shapes: B=32, S=1024, WIN=1024, E=128, H=512, L=3
// ---------------------------------------------------------------------------

// ------------------------- device scratch (no allocs) ----------------------
__device__ float g_embed[(size_t)32768 * 128];        // (B*S, E)
__device__ float g_a1v[(size_t)32768 * 128];          // (B*S, E)
__device__ float g_attn[(size_t)32768 * 3];           // logits (B*S, 3)
__device__ float g_attnT[(size_t)1024 * 3 * 32];      // [t][i][b] softmaxed
__device__ float g_xp[(size_t)32768 * 2048];          // (B*S, 4H) gate pre-act
__device__ float g_xpT[(size_t)1024 * 65536];         // [t][g*32+b]
__device__ float g_encT[(size_t)1025 * 16384];        // [t+1][j*32+b]; slot0 = h0
__device__ float g_ctxT[(size_t)1024 * 16384];        // [t][j*32+b]
__device__ float g_hdT[2][16384];                     // decoder h double buffer
__device__ float g_o1[4096];                          // [b*128+e]
__device__ float g_p[32];
__device__ float g_be[2048];                          // bih_e + bhh_e
__device__ unsigned g_arr0[128], g_arr1[128];
__device__ unsigned g_go0, g_go1;

// ------------------------- grid barrier (flag tree) ------------------------
__device__ __forceinline__ void grid_bar(unsigned* arr, unsigned* go, unsigned tag) {
    __syncthreads();
    if (blockIdx.x == 0) {
        if (threadIdx.x > 0 && threadIdx.x < 128) {
            while (*((volatile unsigned*)&arr[threadIdx.x]) < tag) {}
        }
        __syncthreads();
        if (threadIdx.x == 0) {
            __threadfence();
            *((volatile unsigned*)go) = tag;
        }
    } else {
        if (threadIdx.x == 0) {
            __threadfence();
            *((volatile unsigned*)&arr[blockIdx.x]) = tag;
            while (*((volatile unsigned*)go) < tag) {}
            __threadfence();
        }
    }
    __syncthreads();
}

// ------------------------- prep / init -------------------------------------
__global__ void prep_k(const float* __restrict__ bih_e, const float* __restrict__ bhh_e) {
    int n = blockIdx.x * 256 + threadIdx.x;
    if (n < 2048) g_be[n] = bih_e[n] + bhh_e[n];
}

__global__ void init_k(const float* __restrict__ enc_h0, const float* __restrict__ dec_h0) {
    int n = blockIdx.x * blockDim.x + threadIdx.x;
    int stride = gridDim.x * blockDim.x;
    if (n < 128) { g_arr0[n] = 0u; g_arr1[n] = 0u; }
    if (n == 0) { g_go0 = 0u; g_go1 = 0u; }
    for (int e = n; e < 16384; e += stride) {
        g_encT[e]    = enc_h0[e >> 5];
        g_hdT[0][e]  = dec_h0[e >> 5];
    }
}

// ------------------------- generic fp32 GEMM --------------------------------
// C[M,N] = act(A[M,K] @ W[N,K]^T + bias), 64x64 tiles, 256 threads.
__global__ void __launch_bounds__(256) gemm_k(const float* __restrict__ A,
                                              const float* __restrict__ W,
                                              const float* __restrict__ bias,
                                              float* __restrict__ C,
                                              int M, int N, int K, int relu) {
    __shared__ float As[16][72];
    __shared__ float Ws[16][72];
    int tid = threadIdx.x;
    int tx = tid & 15, ty = tid >> 4;
    int m0 = blockIdx.x * 64, n0 = blockIdx.y * 64;
    int lr = tid >> 2, lc = (tid & 3) << 2;
    const float* Ap = A + (size_t)(m0 + lr) * K + lc;
    const float* Wp = W + (size_t)(n0 + lr) * K + lc;
    float acc[4][4] = {};
    for (int k0 = 0; k0 < K; k0 += 16) {
        float4 a4 = *(const float4*)(Ap + k0);
        float4 w4 = *(const float4*)(Wp + k0);
        __syncthreads();
        As[lc + 0][lr] = a4.x; As[lc + 1][lr] = a4.y; As[lc + 2][lr] = a4.z; As[lc + 3][lr] = a4.w;
        Ws[lc + 0][lr] = w4.x; Ws[lc + 1][lr] = w4.y; Ws[lc + 2][lr] = w4.z; Ws[lc + 3][lr] = w4.w;
        __syncthreads();
#pragma unroll
        for (int kk = 0; kk < 16; kk++) {
            float4 av = *(const float4*)&As[kk][ty << 2];
            float4 wv = *(const float4*)&Ws[kk][tx << 2];
            acc[0][0] = fmaf(av.x, wv.x, acc[0][0]); acc[0][1] = fmaf(av.x, wv.y, acc[0][1]);
            acc[0][2] = fmaf(av.x, wv.z, acc[0][2]); acc[0][3] = fmaf(av.x, wv.w, acc[0][3]);
            acc[1][0] = fmaf(av.y, wv.x, acc[1][0]); acc[1][1] = fmaf(av.y, wv.y, acc[1][1]);
            acc[1][2] = fmaf(av.y, wv.z, acc[1][2]); acc[1][3] = fmaf(av.y, wv.w, acc[1][3]);
            acc[2][0] = fmaf(av.z, wv.x, acc[2][0]); acc[2][1] = fmaf(av.z, wv.y, acc[2][1]);
            acc[2][2] = fmaf(av.z, wv.z, acc[2][2]); acc[2][3] = fmaf(av.z, wv.w, acc[2][3]);
            acc[3][0] = fmaf(av.w, wv.x, acc[3][0]); acc[3][1] = fmaf(av.w, wv.y, acc[3][1]);
            acc[3][2] = fmaf(av.w, wv.z, acc[3][2]); acc[3][3] = fmaf(av.w, wv.w, acc[3][3]);
        }
    }
    float4 bz = *(const float4*)(bias + n0 + (tx << 2));
#pragma unroll
    for (int i = 0; i < 4; i++) {
        float4 o;
        o.x = acc[i][0] + bz.x; o.y = acc[i][1] + bz.y;
        o.z = acc[i][2] + bz.z; o.w = acc[i][3] + bz.w;
        if (relu) {
            o.x = fmaxf(o.x, 0.f); o.y = fmaxf(o.y, 0.f);
            o.z = fmaxf(o.z, 0.f); o.w = fmaxf(o.w, 0.f);
        }
        *(float4*)(C + (size_t)(m0 + (ty << 2) + i) * N + n0 + (tx << 2)) = o;
    }
}

// ------------------------- attention logits (L=3) ---------------------------
__global__ void logits_k(const float* __restrict__ W_a2, const float* __restrict__ b_a2) {
    __shared__ float w[3][128];
    int tt = threadIdx.x;
    if (tt < 128) { w[0][tt] = W_a2[tt]; w[1][tt] = W_a2[128 + tt]; w[2][tt] = W_a2[256 + tt]; }
    __syncthreads();
    int m = blockIdx.x * 256 + tt;
    const float* row = g_a1v + (size_t)m * 128;
    float s0 = b_a2[0], s1 = b_a2[1], s2 = b_a2[2];
#pragma unroll 4
    for (int k = 0; k < 128; k++) {
        float v = row[k];
        s0 = fmaf(v, w[0][k], s0);
        s1 = fmaf(v, w[1][k], s1);
        s2 = fmaf(v, w[2][k], s2);
    }
    g_attn[(size_t)m * 3 + 0] = s0;
    g_attn[(size_t)m * 3 + 1] = s1;
    g_attn[(size_t)m * 3 + 2] = s2;
}

// ------------------------- softmax over TIME (axis=1) -----------------------
__global__ void softmax_k() {
    int b = blockIdx.x, l = blockIdx.y, tt = threadIdx.x;
    __shared__ float red[256];
    float v[4];
    float mx = -1e30f;
#pragma unroll
    for (int i = 0; i < 4; i++) {
        int t = tt + i * 256;
        v[i] = g_attn[((size_t)b * 1024 + t) * 3 + l];
        mx = fmaxf(mx, v[i]);
    }
    red[tt] = mx; __syncthreads();
    for (int s = 128; s > 0; s >>= 1) { if (tt < s) red[tt] = fmaxf(red[tt], red[tt + s]); __syncthreads(); }
    mx = red[0]; __syncthreads();
    float sm = 0.f;
#pragma unroll
    for (int i = 0; i < 4; i++) { v[i] = expf(v[i] - mx); sm += v[i]; }
    red[tt] = sm; __syncthreads();
    for (int s = 128; s > 0; s >>= 1) { if (tt < s) red[tt] += red[tt + s]; __syncthreads(); }
    float inv = 1.f / red[0];
#pragma unroll
    for (int i = 0; i < 4; i++) {
        int t = tt + i * 256;
        g_attnT[((size_t)t * 3 + l) * 32 + b] = v[i] * inv;
    }
}

// ------------------------- x_proj transpose ---------------------------------
// g_xp[(b*1024+t)*2048 + n] -> g_xpT[t*65536 + n*32 + b]
__global__ void transp_k() {
    __shared__ float tile[32][65];
    int t = blockIdx.x;
    int n0 = blockIdx.y * 64;
    int tt = threadIdx.x;
#pragma unroll
    for (int p = 0; p < 8; p++) {
        int e = p * 256 + tt;
        int b = e >> 6, nl = e & 63;
        tile[b][nl] = g_xp[((size_t)b * 1024 + t) * 2048 + n0 + nl];
    }
    __syncthreads();
#pragma unroll
    for (int p = 0; p < 8; p++) {
        int e = p * 256 + tt;
        int nl = e >> 5, b = e & 31;
        g_xpT[(size_t)t * 65536 + (size_t)(n0 + nl) * 32 + b] = tile[b][nl];
    }
}

// ------------------------- encoder LSTM (persistent) ------------------------
__global__ void __launch_bounds__(256, 1) enc_k(const float* __restrict__ Whh_e,
                                                const float* __restrict__ enc_c0) {
    __shared__ float Ws[16 * 512];
    __shared__ float sred[512];
    int tt = threadIdx.x, bid = blockIdx.x;
    int b = tt & 31, jl = (tt >> 5) & 3, half = tt >> 7;
    int j = bid * 4 + jl;
    for (int idx = tt; idx < 16 * 128; idx += 256) {
        int r = idx >> 7, kk = (idx & 127) << 2;
        int q = r & 3, jj = bid * 4 + (r >> 2);
        *(float4*)&Ws[r * 512 + kk] = *(const float4*)&Whh_e[(size_t)(q * 512 + jj) * 512 + kk];
    }
    float c = (half == 0) ? enc_c0[j] : 0.f;
    const float* w0p = &Ws[(jl * 4 + 0) * 512];
    const float* w1p = &Ws[(jl * 4 + 1) * 512];
    const float* w2p = &Ws[(jl * 4 + 2) * 512];
    const float* w3p = &Ws[(jl * 4 + 3) * 512];
    int kbeg = half << 8;
    __syncthreads();
    for (int t = 0; t < 1024; t++) {
        const float* hp = g_encT + (size_t)t * 16384 + b;
        float a0, a1, a2, a3;
        if (half == 0) {
            const float* xp = g_xpT + (size_t)t * 65536 + b;
            a0 = xp[(0 * 512 + j) * 32];
            a1 = xp[(1 * 512 + j) * 32];
            a2 = xp[(2 * 512 + j) * 32];
            a3 = xp[(3 * 512 + j) * 32];
        } else { a0 = a1 = a2 = a3 = 0.f; }
#pragma unroll 2
        for (int k = kbeg; k < kbeg + 256; k += 4) {
            float4 w0 = *(const float4*)&w0p[k];
            float4 w1 = *(const float4*)&w1p[k];
            float4 w2 = *(const float4*)&w2p[k];
            float4 w3 = *(const float4*)&w3p[k];
            float x0 = hp[(k + 0) * 32], x1 = hp[(k + 1) * 32];
            float x2 = hp[(k + 2) * 32], x3 = hp[(k + 3) * 32];
            a0 = fmaf(w0.x, x0, a0); a0 = fmaf(w0.y, x1, a0); a0 = fmaf(w0.z, x2, a0); a0 = fmaf(w0.w, x3, a0);
            a1 = fmaf(w1.x, x0, a1); a1 = fmaf(w1.y, x1, a1); a1 = fmaf(w1.z, x2, a1); a1 = fmaf(w1.w, x3, a1);
            a2 = fmaf(w2.x, x0, a2); a2 = fmaf(w2.y, x1, a2); a2 = fmaf(w2.z, x2, a2); a2 = fmaf(w2.w, x3, a2);
            a3 = fmaf(w3.x, x0, a3); a3 = fmaf(w3.y, x1, a3); a3 = fmaf(w3.z, x2, a3); a3 = fmaf(w3.w, x3, a3);
        }
        if (half) {
            int o = (tt - 128) << 2;
            sred[o + 0] = a0; sred[o + 1] = a1; sred[o + 2] = a2; sred[o + 3] = a3;
        }
        __syncthreads();
        if (!half) {
            int o = tt << 2;
            a0 += sred[o + 0]; a1 += sred[o + 1]; a2 += sred[o + 2]; a3 += sred[o + 3];
            float ig = 1.f / (1.f + expf(-a0));
            float fg = 1.f / (1.f + expf(-a1));
            float gg = tanhf(a2);
            float og = 1.f / (1.f + expf(-a3));
            c = fg * c + ig * gg;
            g_encT[(size_t)(t + 1) * 16384 + j * 32 + b] = og * tanhf(c);
        }
        grid_bar(g_arr0, &g_go0, (unsigned)(t + 1));
    }
}

// ------------------------- convolve + length mask ----------------------------
__global__ void conv_k(const int* __restrict__ lengths) {
    int t = blockIdx.x;
    int base = blockIdx.y * 2048;
#pragma unroll
    for (int p = 0; p < 8; p++) {
        int idx = base + p * 256 + threadIdx.x;
        int b = idx & 31;
        int len = lengths[b];
        float val = 0.f;
#pragma unroll
        for (int i = 0; i < 3; i++) {
            int tp = t - i;
            if (tp >= 0 && tp < len) {
                float a = g_attnT[((size_t)t * 3 + i) * 32 + b];
                val = fmaf(a, g_encT[(size_t)(tp + 1) * 16384 + idx], val);
            }
        }
        g_ctxT[(size_t)t * 16384 + idx] = val;
    }
}

// ------------------------- decoder LSTM + out MLP (persistent) ---------------
extern __shared__ float dsm[];
__global__ void __launch_bounds__(256, 1) dec_k(const float* __restrict__ Wih_d,
                                                const float* __restrict__ Whh_d,
                                                const float* __restrict__ bih_d,
                                                const float* __restrict__ bhh_d,
                                                const float* __restrict__ dec_c0,
                                                const float* __restrict__ W_o1,
                                                const float* __restrict__ b_o1,
                                                const float* __restrict__ W_o2,
                                                const float* __restrict__ b_o2,
                                                const float* __restrict__ mask,
                                                float* __restrict__ out) {
    float* Wxs = dsm;             // [16][512] : Wih_d[:,1:513]
    float* Whs = dsm + 16 * 512;  // [16][512] : Whh_d
    __shared__ float w0s[16], bss[16], sred[512], psm[4];
    int tt = threadIdx.x, bid = blockIdx.x;
    int b = tt & 31, jl = (tt >> 5) & 3, half = tt >> 7;
    int j = bid * 4 + jl;
    for (int idx = tt; idx < 16 * 512; idx += 256) {
        int r = idx >> 9, k = idx & 511;
        int q = r & 3, jj = bid * 4 + (r >> 2);
        Wxs[idx] = Wih_d[(size_t)(q * 512 + jj) * 513 + 1 + k];
    }
    for (int idx = tt; idx < 16 * 128; idx += 256) {
        int r = idx >> 7, kk = (idx & 127) << 2;
        int q = r & 3, jj = bid * 4 + (r >> 2);
        *(float4*)&Whs[r * 512 + kk] = *(const float4*)&Whh_d[(size_t)(q * 512 + jj) * 512 + kk];
    }
    if (tt < 16) {
        int q = tt & 3, jj = bid * 4 + (tt >> 2);
        int g = q * 512 + jj;
        w0s[tt] = Wih_d[(size_t)g * 513];
        bss[tt] = bih_d[g] + bhh_d[g];
    }
    float c = (half == 0) ? dec_c0[j] : 0.f;
    int bo = bid * 32 + (tt >> 3);   // o1 output index [0,4096)
    int sub = tt & 7;
    int ob = bo >> 7, oe = bo & 127;
    const float* wo1 = W_o1 + (size_t)oe * 512;
    __syncthreads();
    int par = 0;
    unsigned tag = 0;
    for (int t = 0; t < 1024; t++) {
        float a0, a1, a2, a3;
        if (!half) {
            float p = (t > 0) ? __ldcg(&g_p[b]) : 0.f;
            a0 = fmaf(p, w0s[jl * 4 + 0], bss[jl * 4 + 0]);
            a1 = fmaf(p, w0s[jl * 4 + 1], bss[jl * 4 + 1]);
            a2 = fmaf(p, w0s[jl * 4 + 2], bss[jl * 4 + 2]);
            a3 = fmaf(p, w0s[jl * 4 + 3], bss[jl * 4 + 3]);
            const float* xp = g_ctxT + (size_t)t * 16384 + b;
            const float* r0 = &Wxs[(jl * 4 + 0) * 512];
            const float* r1 = &Wxs[(jl * 4 + 1) * 512];
            const float* r2 = &Wxs[(jl * 4 + 2) * 512];
            const float* r3 = &Wxs[(jl * 4 + 3) * 512];
#pragma unroll 2
            for (int k = 0; k < 512; k += 4) {
                float4 w0 = *(const float4*)&r0[k];
                float4 w1 = *(const float4*)&r1[k];
                float4 w2 = *(const float4*)&r2[k];
                float4 w3 = *(const float4*)&r3[k];
                float x0 = xp[(k + 0) * 32], x1 = xp[(k + 1) * 32];
                float x2 = xp[(k + 2) * 32], x3 = xp[(k + 3) * 32];
                a0 = fmaf(w0.x, x0, a0); a0 = fmaf(w0.y, x1, a0); a0 = fmaf(w0.z, x2, a0); a0 = fmaf(w0.w, x3, a0);
                a1 = fmaf(w1.x, x0, a1); a1 = fmaf(w1.y, x1, a1); a1 = fmaf(w1.z, x2, a1); a1 = fmaf(w1.w, x3, a1);
                a2 = fmaf(w2.x, x0, a2); a2 = fmaf(w2.y, x1, a2); a2 = fmaf(w2.z, x2, a2); a2 = fmaf(w2.w, x3, a2);
                a3 = fmaf(w3.x, x0, a3); a3 = fmaf(w3.y, x1, a3); a3 = fmaf(w3.z, x2, a3); a3 = fmaf(w3.w, x3, a3);
            }
        } else {
            a0 = a1 = a2 = a3 = 0.f;
            const float* hp = g_hdT[par] + b;
            const float* r0 = &Whs[(jl * 4 + 0) * 512];
            const float* r1 = &Whs[(jl * 4 + 1) * 512];
            const float* r2 = &Whs[(jl * 4 + 2) * 512];
            const float* r3 = &Whs[(jl * 4 + 3) * 512];
#pragma unroll 2
            for (int k = 0; k < 512; k += 4) {
                float4 w0 = *(const float4*)&r0[k];
                float4 w1 = *(const float4*)&r1[k];
                float4 w2 = *(const float4*)&r2[k];
                float4 w3 = *(const float4*)&r3[k];
                float x0 = __ldcg(&hp[(k + 0) * 32]), x1 = __ldcg(&hp[(k + 1) * 32]);
                float x2 = __ldcg(&hp[(k + 2) * 32]), x3 = __ldcg(&hp[(k + 3) * 32]);
                a0 = fmaf(w0.x, x0, a0); a0 = fmaf(w0.y, x1, a0); a0 = fmaf(w0.z, x2, a0); a0 = fmaf(w0.w, x3, a0);
                a1 = fmaf(w1.x, x0, a1); a1 = fmaf(w1.y, x1, a1); a1 = fmaf(w1.z, x2, a1); a1 = fmaf(w1.w, x3, a1);
                a2 = fmaf(w2.x, x0, a2); a2 = fmaf(w2.y, x1, a2); a2 = fmaf(w2.z, x2, a2); a2 = fmaf(w2.w, x3, a2);
                a3 = fmaf(w3.x, x0, a3); a3 = fmaf(w3.y, x1, a3); a3 = fmaf(w3.z, x2, a3); a3 = fmaf(w3.w, x3, a3);
            }
        }
        if (half) {
            int o = (tt - 128) << 2;
            sred[o + 0] = a0; sred[o + 1] = a1; sred[o + 2] = a2; sred[o + 3] = a3;
        }
        __syncthreads();
        if (!half) {
            int o = tt << 2;
            a0 += sred[o + 0]; a1 += sred[o + 1]; a2 += sred[o + 2]; a3 += sred[o + 3];
            float ig = 1.f / (1.f + expf(-a0));
            float fg = 1.f / (1.f + expf(-a1));
            float gg = tanhf(a2);
            float og = 1.f / (1.f + expf(-a3));
            c = fg * c + ig * gg;
            g_hdT[par ^ 1][j * 32 + b] = og * tanhf(c);
        }
        tag++; grid_bar(g_arr1, &g_go1, tag);

        // ---- o1 = relu(W_o1 @ h + b_o1), distributed 8 threads/output ----
        {
            const float* hnew = g_hdT[par ^ 1];
            float s = 0.f;
            int k2b = sub * 64;
#pragma unroll 4
            for (int k2 = k2b; k2 < k2b + 64; k2++)
                s = fmaf(wo1[k2], __ldcg(&hnew[k2 * 32 + ob]), s);
            s += __shfl_xor_sync(0xffffffffu, s, 1);
            s += __shfl_xor_sync(0xffffffffu, s, 2);
            s += __shfl_xor_sync(0xffffffffu, s, 4);
            if (sub == 0) g_o1[bo] = fmaxf(s + b_o1[oe], 0.f);
        }
        tag++; grid_bar(g_arr1, &g_go1, tag);

        // ---- p = o1 @ W_o2 + b_o2 (blocks 0..31 = batch), write output ----
        if (bid < 32 && tt < 128) {
            float v = __ldcg(&g_o1[bid * 128 + tt]) * W_o2[tt];
            v += __shfl_xor_sync(0xffffffffu, v, 16);
            v += __shfl_xor_sync(0xffffffffu, v, 8);
            v += __shfl_xor_sync(0xffffffffu, v, 4);
            v += __shfl_xor_sync(0xffffffffu, v, 2);
            v += __shfl_xor_sync(0xffffffffu, v, 1);
            if ((tt & 31) == 0) psm[tt >> 5] = v;
        }
        __syncthreads();
        if (bid < 32 && tt == 0) {
            float p = psm[0] + psm[1] + psm[2] + psm[3] + b_o2[0];
            g_p[bid] = p;
            out[bid * 1024 + t] = p * mask[bid * 1024 + t];
        }
        tag++; grid_bar(g_arr1, &g_go1, tag);
        par ^= 1;
    }
}

// ---------------------------------------------------------------------------
extern "C" void kernel_launch(void* const* d_in, const int* in_sizes, int n_in,
                              void* d_out, int out_size) {
    const float* inputs = (const float*)d_in[0];
    const float* mask   = (const float*)d_in[1];
    const int*   lengths= (const int*)d_in[2];
    const float* W_e    = (const float*)d_in[3];
    const float* b_e    = (const float*)d_in[4];
    const float* W_a1   = (const float*)d_in[5];
    const float* b_a1   = (const float*)d_in[6];
    const float* W_a2   = (const float*)d_in[7];
    const float* b_a2   = (const float*)d_in[8];
    const float* Wih_e  = (const float*)d_in[9];
    const float* Whh_e  = (const float*)d_in[10];
    const float* bih_e  = (const float*)d_in[11];
    const float* bhh_e  = (const float*)d_in[12];
    const float* enc_h0 = (const float*)d_in[13];
    const float* enc_c0 = (const float*)d_in[14];
    const float* Wih_d  = (const float*)d_in[15];
    const float* Whh_d  = (const float*)d_in[16];
    const float* bih_d  = (const float*)d_in[17];
    const float* bhh_d  = (const float*)d_in[18];
    const float* dec_h0 = (const float*)d_in[19];
    const float* dec_c0 = (const float*)d_in[20];
    const float* W_o1   = (const float*)d_in[21];
    const float* b_o1   = (const float*)d_in[22];
    const float* W_o2   = (const float*)d_in[23];
    const float* b_o2   = (const float*)d_in[24];
    float* out = (float*)d_out;

    cudaFuncSetAttribute(dec_k, cudaFuncAttributeMaxDynamicSharedMemorySize, 65536);

    void *p_embed, *p_a1v, *p_xp, *p_be;
    cudaGetSymbolAddress(&p_embed, g_embed);
    cudaGetSymbolAddress(&p_a1v, g_a1v);
    cudaGetSymbolAddress(&p_xp, g_xp);
    cudaGetSymbolAddress(&p_be, g_be);

    prep_k<<<8, 256>>>(bih_e, bhh_e);
    init_k<<<64, 256>>>(enc_h0, dec_h0);

    // embed = relu(inputs @ W_e^T + b_e)
    gemm_k<<<dim3(512, 2), 256>>>(inputs, W_e, b_e, (float*)p_embed, 32768, 128, 1024, 1);
    // a1 = relu(embed @ W_a1^T + b_a1)
    gemm_k<<<dim3(512, 2), 256>>>((const float*)p_embed, W_a1, b_a1, (float*)p_a1v, 32768, 128, 128, 1);
    // attention logits + softmax over time
    logits_k<<<128, 256>>>(W_a2, b_a2);
    softmax_k<<<dim3(32, 3), 256>>>();
    // x_proj = embed @ Wih_e^T + (bih_e + bhh_e)
    gemm_k<<<dim3(512, 32), 256>>>((const float*)p_embed, Wih_e, (const float*)p_be, (float*)p_xp, 32768, 2048, 128, 0);
    transp_k<<<dim3(1024, 32), 256>>>();
    // encoder LSTM (persistent, grid barrier per step)
    enc_k<<<128, 256>>>(Whh_e, enc_c0);
    // context = local attention over encoder outputs (with length mask)
    conv_k<<<dim3(1024, 8), 256>>>(lengths);
    // decoder LSTM + output MLP (persistent, 3 barriers per step)
    dec_k<<<128, 256, 65536>>>(Wih_d, Whh_d, bih_d, bhh_d, dec_c0,
                               W_o1, b_o1, W_o2, b_o2, mask, out);
}

// round 13
// speedup vs baseline: 2.3769x; 2.3769x over previous
#include <cuda_runtime.h>
#include <math.h>
#include <stdint.h>
#include <stddef.h>

// ---------------------------------------------------------------------------
// Shapes: B=32, S=1024, WIN=1024, E=128, H=512, L=3
// ---------------------------------------------------------------------------

// ------------------------- device scratch (no allocs) ----------------------
__device__ float g_embed[(size_t)32768 * 128];        // (B*S, E)
__device__ float g_a1v[(size_t)32768 * 128];          // (B*S, E)
__device__ float g_attn[(size_t)32768 * 3];           // logits (B*S, 3)
__device__ float g_attnT[(size_t)1024 * 3 * 32];      // [t][i][b] softmaxed
__device__ float g_xp[(size_t)32768 * 2048];          // (B*S, 4H) gate pre-act
__device__ float g_xpT[(size_t)1024 * 65536];         // [t][g*32+b]
__device__ float g_encT[(size_t)1025 * 16384];        // [t+1][j*32+b]; slot0 = h0
__device__ float g_ctxT[(size_t)1024 * 16384];        // [t][j*32+b]
__device__ float g_hdT[2][16384];                     // decoder h double buffer
__device__ float g_wo1T[512 * 128];                   // W_o1 transposed [k][e]
__device__ float g_be[2048];                          // bih_e + bhh_e
__device__ unsigned long long g_pq[32];               // packed (tag<<32)|p_bits
__device__ unsigned g_arr0[128], g_arr1[128];
__device__ unsigned g_go0, g_go1;

// ------------------------- split-phase grid barrier -------------------------
__device__ __forceinline__ void bar_arrive(unsigned* arr, unsigned tag) {
    __syncthreads();
    __threadfence();
    if (blockIdx.x != 0 && threadIdx.x == 0)
        *((volatile unsigned*)&arr[blockIdx.x]) = tag;
}

__device__ __forceinline__ void bar_wait(unsigned* arr, unsigned* go, unsigned tag) {
    if (blockIdx.x == 0) {
        if (threadIdx.x > 0 && threadIdx.x < 128) {
            while (*((volatile unsigned*)&arr[threadIdx.x]) < tag) {}
        }
        __syncthreads();
        if (threadIdx.x == 0) *((volatile unsigned*)go) = tag;
    } else {
        if (threadIdx.x == 0) {
            while (*((volatile unsigned*)go) < tag) {}
            __threadfence();
        }
        __syncthreads();
    }
}

// ------------------------- prep / init -------------------------------------
__global__ void prep_k(const float* __restrict__ bih_e, const float* __restrict__ bhh_e) {
    int n = blockIdx.x * 256 + threadIdx.x;
    if (n < 2048) g_be[n] = bih_e[n] + bhh_e[n];
}

__global__ void wo1t_k(const float* __restrict__ W_o1) {
    int n = blockIdx.x * 256 + threadIdx.x;   // 65536 elems
    int e = n >> 9, k = n & 511;
    g_wo1T[k * 128 + e] = W_o1[n];
}

__global__ void init_k(const float* __restrict__ enc_h0, const float* __restrict__ dec_h0) {
    int n = blockIdx.x * blockDim.x + threadIdx.x;
    int stride = gridDim.x * blockDim.x;
    if (n < 128) { g_arr0[n] = 0u; g_arr1[n] = 0u; }
    if (n < 32)  g_pq[n] = 0ull;
    if (n == 0) { g_go0 = 0u; g_go1 = 0u; }
    for (int e = n; e < 16384; e += stride) {
        g_encT[e]   = enc_h0[e >> 5];
        g_hdT[0][e] = dec_h0[e >> 5];
    }
}

// ------------------------- generic fp32 GEMM --------------------------------
__global__ void __launch_bounds__(256) gemm_k(const float* __restrict__ A,
                                              const float* __restrict__ W,
                                              const float* __restrict__ bias,
                                              float* __restrict__ C,
                                              int M, int N, int K, int relu) {
    __shared__ float As[16][72];
    __shared__ float Ws[16][72];
    int tid = threadIdx.x;
    int tx = tid & 15, ty = tid >> 4;
    int m0 = blockIdx.x * 64, n0 = blockIdx.y * 64;
    int lr = tid >> 2, lc = (tid & 3) << 2;
    const float* Ap = A + (size_t)(m0 + lr) * K + lc;
    const float* Wp = W + (size_t)(n0 + lr) * K + lc;
    float acc[4][4] = {};
    for (int k0 = 0; k0 < K; k0 += 16) {
        float4 a4 = *(const float4*)(Ap + k0);
        float4 w4 = *(const float4*)(Wp + k0);
        __syncthreads();
        As[lc + 0][lr] = a4.x; As[lc + 1][lr] = a4.y; As[lc + 2][lr] = a4.z; As[lc + 3][lr] = a4.w;
        Ws[lc + 0][lr] = w4.x; Ws[lc + 1][lr] = w4.y; Ws[lc + 2][lr] = w4.z; Ws[lc + 3][lr] = w4.w;
        __syncthreads();
#pragma unroll
        for (int kk = 0; kk < 16; kk++) {
            float4 av = *(const float4*)&As[kk][ty << 2];
            float4 wv = *(const float4*)&Ws[kk][tx << 2];
            acc[0][0] = fmaf(av.x, wv.x, acc[0][0]); acc[0][1] = fmaf(av.x, wv.y, acc[0][1]);
            acc[0][2] = fmaf(av.x, wv.z, acc[0][2]); acc[0][3] = fmaf(av.x, wv.w, acc[0][3]);
            acc[1][0] = fmaf(av.y, wv.x, acc[1][0]); acc[1][1] = fmaf(av.y, wv.y, acc[1][1]);
            acc[1][2] = fmaf(av.y, wv.z, acc[1][2]); acc[1][3] = fmaf(av.y, wv.w, acc[1][3]);
            acc[2][0] = fmaf(av.z, wv.x, acc[2][0]); acc[2][1] = fmaf(av.z, wv.y, acc[2][1]);
            acc[2][2] = fmaf(av.z, wv.z, acc[2][2]); acc[2][3] = fmaf(av.z, wv.w, acc[2][3]);
            acc[3][0] = fmaf(av.w, wv.x, acc[3][0]); acc[3][1] = fmaf(av.w, wv.y, acc[3][1]);
            acc[3][2] = fmaf(av.w, wv.z, acc[3][2]); acc[3][3] = fmaf(av.w, wv.w, acc[3][3]);
        }
    }
    float4 bz = *(const float4*)(bias + n0 + (tx << 2));
#pragma unroll
    for (int i = 0; i < 4; i++) {
        float4 o;
        o.x = acc[i][0] + bz.x; o.y = acc[i][1] + bz.y;
        o.z = acc[i][2] + bz.z; o.w = acc[i][3] + bz.w;
        if (relu) {
            o.x = fmaxf(o.x, 0.f); o.y = fmaxf(o.y, 0.f);
            o.z = fmaxf(o.z, 0.f); o.w = fmaxf(o.w, 0.f);
        }
        *(float4*)(C + (size_t)(m0 + (ty << 2) + i) * N + n0 + (tx << 2)) = o;
    }
}

// ------------------------- attention logits (L=3) ---------------------------
__global__ void logits_k(const float* __restrict__ W_a2, const float* __restrict__ b_a2) {
    __shared__ float w[3][128];
    int tt = threadIdx.x;
    if (tt < 128) { w[0][tt] = W_a2[tt]; w[1][tt] = W_a2[128 + tt]; w[2][tt] = W_a2[256 + tt]; }
    __syncthreads();
    int m = blockIdx.x * 256 + tt;
    const float* row = g_a1v + (size_t)m * 128;
    float s0 = b_a2[0], s1 = b_a2[1], s2 = b_a2[2];
#pragma unroll 4
    for (int k = 0; k < 128; k++) {
        float v = row[k];
        s0 = fmaf(v, w[0][k], s0);
        s1 = fmaf(v, w[1][k], s1);
        s2 = fmaf(v, w[2][k], s2);
    }
    g_attn[(size_t)m * 3 + 0] = s0;
    g_attn[(size_t)m * 3 + 1] = s1;
    g_attn[(size_t)m * 3 + 2] = s2;
}

// ------------------------- softmax over TIME (axis=1) -----------------------
__global__ void softmax_k() {
    int b = blockIdx.x, l = blockIdx.y, tt = threadIdx.x;
    __shared__ float red[256];
    float v[4];
    float mx = -1e30f;
#pragma unroll
    for (int i = 0; i < 4; i++) {
        int t = tt + i * 256;
        v[i] = g_attn[((size_t)b * 1024 + t) * 3 + l];
        mx = fmaxf(mx, v[i]);
    }
    red[tt] = mx; __syncthreads();
    for (int s = 128; s > 0; s >>= 1) { if (tt < s) red[tt] = fmaxf(red[tt], red[tt + s]); __syncthreads(); }
    mx = red[0]; __syncthreads();
    float sm = 0.f;
#pragma unroll
    for (int i = 0; i < 4; i++) { v[i] = expf(v[i] - mx); sm += v[i]; }
    red[tt] = sm; __syncthreads();
    for (int s = 128; s > 0; s >>= 1) { if (tt < s) red[tt] += red[tt + s]; __syncthreads(); }
    float inv = 1.f / red[0];
#pragma unroll
    for (int i = 0; i < 4; i++) {
        int t = tt + i * 256;
        g_attnT[((size_t)t * 3 + l) * 32 + b] = v[i] * inv;
    }
}

// ------------------------- x_proj transpose ---------------------------------
__global__ void transp_k() {
    __shared__ float tile[32][65];
    int t = blockIdx.x;
    int n0 = blockIdx.y * 64;
    int tt = threadIdx.x;
#pragma unroll
    for (int p = 0; p < 8; p++) {
        int e = p * 256 + tt;
        int b = e >> 6, nl = e & 63;
        tile[b][nl] = g_xp[((size_t)b * 1024 + t) * 2048 + n0 + nl];
    }
    __syncthreads();
#pragma unroll
    for (int p = 0; p < 8; p++) {
        int e = p * 256 + tt;
        int nl = e >> 5, b = e & 31;
        g_xpT[(size_t)t * 65536 + (size_t)(n0 + nl) * 32 + b] = tile[b][nl];
    }
}

// ------------------------- encoder LSTM (persistent) ------------------------
extern __shared__ float dsm[];
__global__ void __launch_bounds__(256, 1) enc_k(const float* __restrict__ Whh_e,
                                                const float* __restrict__ enc_c0) {
    float* Ws = dsm;             // 8192 floats  : 16 gate-rows x 512
    float* hs = dsm + 8192;      // 16384 floats : staged h [k*32+b]
    __shared__ float sred[512];
    int tt = threadIdx.x, bid = blockIdx.x;
    int b = tt & 31, jl = (tt >> 5) & 3, half = tt >> 7;
    int j = bid * 4 + jl;
    for (int idx = tt; idx < 16 * 128; idx += 256) {
        int r = idx >> 7, kk = (idx & 127) << 2;
        int q = r & 3, jj = bid * 4 + (r >> 2);
        *(float4*)&Ws[r * 512 + kk] = *(const float4*)&Whh_e[(size_t)(q * 512 + jj) * 512 + kk];
    }
    float c = (half == 0) ? enc_c0[j] : 0.f;
    const float* w0p = &Ws[(jl * 4 + 0) * 512];
    const float* w1p = &Ws[(jl * 4 + 1) * 512];
    const float* w2p = &Ws[(jl * 4 + 2) * 512];
    const float* w3p = &Ws[(jl * 4 + 3) * 512];
    int kbeg = half << 8;
    __syncthreads();
    for (int t = 0; t < 1024; t++) {
        // independent x-gate loads issued before the barrier wait
        float a0, a1, a2, a3;
        if (half == 0) {
            const float* xp = g_xpT + (size_t)t * 65536 + b;
            a0 = xp[(0 * 512 + j) * 32];
            a1 = xp[(1 * 512 + j) * 32];
            a2 = xp[(2 * 512 + j) * 32];
            a3 = xp[(3 * 512 + j) * 32];
        } else { a0 = a1 = a2 = a3 = 0.f; }
        if (t > 0) bar_wait(g_arr0, &g_go0, (unsigned)t);
        // stage h_{t} input slice into smem (addresses unique per t -> plain ld)
        {
            const float4* src = (const float4*)(g_encT + (size_t)t * 16384);
            float4* dst = (float4*)hs;
#pragma unroll
            for (int i = tt; i < 4096; i += 256) dst[i] = src[i];
        }
        __syncthreads();
        const float* hp = hs + b;
#pragma unroll 2
        for (int k = kbeg; k < kbeg + 256; k += 4) {
            float4 w0 = *(const float4*)&w0p[k];
            float4 w1 = *(const float4*)&w1p[k];
            float4 w2 = *(const float4*)&w2p[k];
            float4 w3 = *(const float4*)&w3p[k];
            float x0 = hp[(k + 0) * 32], x1 = hp[(k + 1) * 32];
            float x2 = hp[(k + 2) * 32], x3 = hp[(k + 3) * 32];
            a0 = fmaf(w0.x, x0, a0); a0 = fmaf(w0.y, x1, a0); a0 = fmaf(w0.z, x2, a0); a0 = fmaf(w0.w, x3, a0);
            a1 = fmaf(w1.x, x0, a1); a1 = fmaf(w1.y, x1, a1); a1 = fmaf(w1.z, x2, a1); a1 = fmaf(w1.w, x3, a1);
            a2 = fmaf(w2.x, x0, a2); a2 = fmaf(w2.y, x1, a2); a2 = fmaf(w2.z, x2, a2); a2 = fmaf(w2.w, x3, a2);
            a3 = fmaf(w3.x, x0, a3); a3 = fmaf(w3.y, x1, a3); a3 = fmaf(w3.z, x2, a3); a3 = fmaf(w3.w, x3, a3);
        }
        if (half) {
            int o = (tt - 128) << 2;
            sred[o + 0] = a0; sred[o + 1] = a1; sred[o + 2] = a2; sred[o + 3] = a3;
        }
        __syncthreads();
        if (!half) {
            int o = tt << 2;
            a0 += sred[o + 0]; a1 += sred[o + 1]; a2 += sred[o + 2]; a3 += sred[o + 3];
            float ig = 1.f / (1.f + expf(-a0));
            float fg = 1.f / (1.f + expf(-a1));
            float gg = tanhf(a2);
            float og = 1.f / (1.f + expf(-a3));
            c = fg * c + ig * gg;
            g_encT[(size_t)(t + 1) * 16384 + j * 32 + b] = og * tanhf(c);
        }
        bar_arrive(g_arr0, (unsigned)(t + 1));
    }
}

// ------------------------- convolve + length mask ----------------------------
__global__ void conv_k(const int* __restrict__ lengths) {
    int t = blockIdx.x;
    int base = blockIdx.y * 2048;
#pragma unroll
    for (int p = 0; p < 8; p++) {
        int idx = base + p * 256 + threadIdx.x;
        int b = idx & 31;
        int len = lengths[b];
        float val = 0.f;
#pragma unroll
        for (int i = 0; i < 3; i++) {
            int tp = t - i;
            if (tp >= 0 && tp < len) {
                float a = g_attnT[((size_t)t * 3 + i) * 32 + b];
                val = fmaf(a, g_encT[(size_t)(tp + 1) * 16384 + idx], val);
            }
        }
        g_ctxT[(size_t)t * 16384 + idx] = val;
    }
}

// ------------------------- decoder LSTM + out MLP (persistent) ---------------
__global__ void __launch_bounds__(256, 1) dec_k(const float* __restrict__ Wih_d,
                                                const float* __restrict__ Whh_d,
                                                const float* __restrict__ bih_d,
                                                const float* __restrict__ bhh_d,
                                                const float* __restrict__ dec_c0,
                                                const float* __restrict__ b_o1,
                                                const float* __restrict__ W_o2,
                                                const float* __restrict__ b_o2,
                                                const float* __restrict__ mask,
                                                float* __restrict__ out) {
    float* Wxs = dsm;             // 8192  : Wih_d[:,1:513] gate rows
    float* Whs = dsm + 8192;      // 8192  : Whh_d gate rows
    float* hs  = dsm + 16384;     // 16384 : staged h_{t-1} [k*32+b]
    float* cs  = dsm + 32768;     // 16384 : staged ctx_t   [k*32+b]
    __shared__ float sred[512], o1part[256];
    __shared__ float w0s[16], bss[16], wo2s[128], bo1s[128];
    int tt = threadIdx.x, bid = blockIdx.x;
    int b = tt & 31, jl = (tt >> 5) & 3, half = tt >> 7;
    int j = bid * 4 + jl;
    for (int idx = tt; idx < 16 * 512; idx += 256) {
        int r = idx >> 9, k = idx & 511;
        int q = r & 3, jj = bid * 4 + (r >> 2);
        Wxs[idx] = Wih_d[(size_t)(q * 512 + jj) * 513 + 1 + k];
    }
    for (int idx = tt; idx < 16 * 128; idx += 256) {
        int r = idx >> 7, kk = (idx & 127) << 2;
        int q = r & 3, jj = bid * 4 + (r >> 2);
        *(float4*)&Whs[r * 512 + kk] = *(const float4*)&Whh_d[(size_t)(q * 512 + jj) * 512 + kk];
    }
    if (tt < 16) {
        int q = tt & 3, jj = bid * 4 + (tt >> 2);
        int g = q * 512 + jj;
        w0s[tt] = Wih_d[(size_t)g * 513];
        bss[tt] = bih_d[g] + bhh_d[g];
    }
    if (bid < 32 && tt < 128) { bo1s[tt] = b_o1[tt]; wo2s[tt] = W_o2[tt]; }
    float c = (half == 0) ? dec_c0[j] : 0.f;
    __syncthreads();
    int par = 0;
    for (int t = 0; t < 1024; t++) {
        // stage ctx_t (independent of the barrier -> hides barrier latency)
        {
            const float4* cg = (const float4*)(g_ctxT + (size_t)t * 16384);
            float4* cd = (float4*)cs;
#pragma unroll
            for (int i = tt; i < 4096; i += 256) cd[i] = cg[i];
        }
        if (t > 0) bar_wait(g_arr1, &g_go1, (unsigned)t);
        // stage h_{t-1} (reused buffer -> must bypass L1)
        {
            const float4* hg = (const float4*)(g_hdT[par]);
            float4* hd = (float4*)hs;
#pragma unroll
            for (int i = tt; i < 4096; i += 256) hd[i] = __ldcg(&hg[i]);
        }
        __syncthreads();
        // batch blocks publish p_{t-1} BEFORE their gate dots
        if (bid < 32 && t > 0) {
            int w = tt >> 5, lane = tt & 31;
            int e = ((w & 3) << 5) + lane;
            int k0 = (w >> 2) << 8;
            float s0 = 0.f, s1 = 0.f, s2 = 0.f, s3 = 0.f;
            const float* wo = g_wo1T + e;
#pragma unroll 4
            for (int k = k0; k < k0 + 256; k += 4) {
                s0 = fmaf(wo[(size_t)(k + 0) * 128], hs[(k + 0) * 32 + bid], s0);
                s1 = fmaf(wo[(size_t)(k + 1) * 128], hs[(k + 1) * 32 + bid], s1);
                s2 = fmaf(wo[(size_t)(k + 2) * 128], hs[(k + 2) * 32 + bid], s2);
                s3 = fmaf(wo[(size_t)(k + 3) * 128], hs[(k + 3) * 32 + bid], s3);
            }
            o1part[((w >> 2) << 7) + e] = (s0 + s1) + (s2 + s3);
            __syncthreads();
            if (tt < 32) {
                float acc = 0.f;
#pragma unroll
                for (int m = 0; m < 4; m++) {
                    int e2 = (m << 5) + tt;
                    float v = fmaxf(o1part[e2] + o1part[128 + e2] + bo1s[e2], 0.f);
                    acc = fmaf(v, wo2s[e2], acc);
                }
                acc += __shfl_xor_sync(0xffffffffu, acc, 16);
                acc += __shfl_xor_sync(0xffffffffu, acc, 8);
                acc += __shfl_xor_sync(0xffffffffu, acc, 4);
                acc += __shfl_xor_sync(0xffffffffu, acc, 2);
                acc += __shfl_xor_sync(0xffffffffu, acc, 1);
                if (tt == 0) {
                    float p = acc + b_o2[0];
                    out[bid * 1024 + (t - 1)] = p * mask[bid * 1024 + (t - 1)];
                    unsigned long long q = ((unsigned long long)(unsigned)t << 32)
                                         | (unsigned long long)__float_as_uint(p);
                    *((volatile unsigned long long*)&g_pq[bid]) = q;
                }
            }
        }
        // gate dots: half0 = ctx part (from cs), half1 = h part (from hs)
        float a0, a1, a2, a3;
        {
            const float* src = half ? (hs + b) : (cs + b);
            const float* wbase = half ? Whs : Wxs;
            const float* r0 = &wbase[(jl * 4 + 0) * 512];
            const float* r1 = &wbase[(jl * 4 + 1) * 512];
            const float* r2 = &wbase[(jl * 4 + 2) * 512];
            const float* r3 = &wbase[(jl * 4 + 3) * 512];
            a0 = half ? 0.f : bss[jl * 4 + 0];
            a1 = half ? 0.f : bss[jl * 4 + 1];
            a2 = half ? 0.f : bss[jl * 4 + 2];
            a3 = half ? 0.f : bss[jl * 4 + 3];
#pragma unroll 2
            for (int k = 0; k < 512; k += 4) {
                float4 w0 = *(const float4*)&r0[k];
                float4 w1 = *(const float4*)&r1[k];
                float4 w2 = *(const float4*)&r2[k];
                float4 w3 = *(const float4*)&r3[k];
                float x0 = src[(k + 0) * 32], x1 = src[(k + 1) * 32];
                float x2 = src[(k + 2) * 32], x3 = src[(k + 3) * 32];
                a0 = fmaf(w0.x, x0, a0); a0 = fmaf(w0.y, x1, a0); a0 = fmaf(w0.z, x2, a0); a0 = fmaf(w0.w, x3, a0);
                a1 = fmaf(w1.x, x0, a1); a1 = fmaf(w1.y, x1, a1); a1 = fmaf(w1.z, x2, a1); a1 = fmaf(w1.w, x3, a1);
                a2 = fmaf(w2.x, x0, a2); a2 = fmaf(w2.y, x1, a2); a2 = fmaf(w2.z, x2, a2); a2 = fmaf(w2.w, x3, a2);
                a3 = fmaf(w3.x, x0, a3); a3 = fmaf(w3.y, x1, a3); a3 = fmaf(w3.z, x2, a3); a3 = fmaf(w3.w, x3, a3);
            }
        }
        if (half) {
            int o = (tt - 128) << 2;
            sred[o + 0] = a0; sred[o + 1] = a1; sred[o + 2] = a2; sred[o + 3] = a3;
        }
        __syncthreads();
        if (!half) {
            int o = tt << 2;
            a0 += sred[o + 0]; a1 += sred[o + 1]; a2 += sred[o + 2]; a3 += sred[o + 3];
            // late rank-1 p term: poll the packed flag (usually long ready)
            if (t > 0) {
                unsigned long long q;
                do { q = *((volatile unsigned long long*)&g_pq[b]); }
                while ((unsigned)(q >> 32) != (unsigned)t);
                float pv = __uint_as_float((unsigned)q);
                a0 = fmaf(pv, w0s[jl * 4 + 0], a0);
                a1 = fmaf(pv, w0s[jl * 4 + 1], a1);
                a2 = fmaf(pv, w0s[jl * 4 + 2], a2);
                a3 = fmaf(pv, w0s[jl * 4 + 3], a3);
            }
            float ig = 1.f / (1.f + expf(-a0));
            float fg = 1.f / (1.f + expf(-a1));
            float gg = tanhf(a2);
            float og = 1.f / (1.f + expf(-a3));
            c = fg * c + ig * gg;
            g_hdT[par ^ 1][j * 32 + b] = og * tanhf(c);
        }
        bar_arrive(g_arr1, (unsigned)(t + 1));
        par ^= 1;
    }
    // ---- epilog: p_1023 from h_1023 (batch blocks; block0 serves barrier) ----
    bar_wait(g_arr1, &g_go1, 1024u);
    if (bid < 32) {
        {
            const float4* hg = (const float4*)(g_hdT[par]);
            float4* hd = (float4*)hs;
#pragma unroll
            for (int i = tt; i < 4096; i += 256) hd[i] = __ldcg(&hg[i]);
        }
        __syncthreads();
        int w = tt >> 5, lane = tt & 31;
        int e = ((w & 3) << 5) + lane;
        int k0 = (w >> 2) << 8;
        float s0 = 0.f, s1 = 0.f, s2 = 0.f, s3 = 0.f;
        const float* wo = g_wo1T + e;
#pragma unroll 4
        for (int k = k0; k < k0 + 256; k += 4) {
            s0 = fmaf(wo[(size_t)(k + 0) * 128], hs[(k + 0) * 32 + bid], s0);
            s1 = fmaf(wo[(size_t)(k + 1) * 128], hs[(k + 1) * 32 + bid], s1);
            s2 = fmaf(wo[(size_t)(k + 2) * 128], hs[(k + 2) * 32 + bid], s2);
            s3 = fmaf(wo[(size_t)(k + 3) * 128], hs[(k + 3) * 32 + bid], s3);
        }
        o1part[((w >> 2) << 7) + e] = (s0 + s1) + (s2 + s3);
        __syncthreads();
        if (tt < 32) {
            float acc = 0.f;
#pragma unroll
            for (int m = 0; m < 4; m++) {
                int e2 = (m << 5) + tt;
                float v = fmaxf(o1part[e2] + o1part[128 + e2] + bo1s[e2], 0.f);
                acc = fmaf(v, wo2s[e2], acc);
            }
            acc += __shfl_xor_sync(0xffffffffu, acc, 16);
            acc += __shfl_xor_sync(0xffffffffu, acc, 8);
            acc += __shfl_xor_sync(0xffffffffu, acc, 4);
            acc += __shfl_xor_sync(0xffffffffu, acc, 2);
            acc += __shfl_xor_sync(0xffffffffu, acc, 1);
            if (tt == 0) {
                float p = acc + b_o2[0];
                out[bid * 1024 + 1023] = p * mask[bid * 1024 + 1023];
            }
        }
    }
}

// ---------------------------------------------------------------------------
extern "C" void kernel_launch(void* const* d_in, const int* in_sizes, int n_in,
                              void* d_out, int out_size) {
    const float* inputs = (const float*)d_in[0];
    const float* mask   = (const float*)d_in[1];
    const int*   lengths= (const int*)d_in[2];
    const float* W_e    = (const float*)d_in[3];
    const float* b_e    = (const float*)d_in[4];
    const float* W_a1   = (const float*)d_in[5];
    const float* b_a1   = (const float*)d_in[6];
    const float* W_a2   = (const float*)d_in[7];
    const float* b_a2   = (const float*)d_in[8];
    const float* Wih_e  = (const float*)d_in[9];
    const float* Whh_e  = (const float*)d_in[10];
    const float* bih_e  = (const float*)d_in[11];
    const float* bhh_e  = (const float*)d_in[12];
    const float* enc_h0 = (const float*)d_in[13];
    const float* enc_c0 = (const float*)d_in[14];
    const float* Wih_d  = (const float*)d_in[15];
    const float* Whh_d  = (const float*)d_in[16];
    const float* bih_d  = (const float*)d_in[17];
    const float* bhh_d  = (const float*)d_in[18];
    const float* dec_h0 = (const float*)d_in[19];
    const float* dec_c0 = (const float*)d_in[20];
    const float* W_o1   = (const float*)d_in[21];
    const float* b_o1   = (const float*)d_in[22];
    const float* W_o2   = (const float*)d_in[23];
    const float* b_o2   = (const float*)d_in[24];
    float* out = (float*)d_out;

    cudaFuncSetAttribute(enc_k, cudaFuncAttributeMaxDynamicSharedMemorySize, 98304);
    cudaFuncSetAttribute(dec_k, cudaFuncAttributeMaxDynamicSharedMemorySize, 196608);

    void *p_embed, *p_a1v, *p_xp, *p_be;
    cudaGetSymbolAddress(&p_embed, g_embed);
    cudaGetSymbolAddress(&p_a1v, g_a1v);
    cudaGetSymbolAddress(&p_xp, g_xp);
    cudaGetSymbolAddress(&p_be, g_be);

    prep_k<<<8, 256>>>(bih_e, bhh_e);
    wo1t_k<<<256, 256>>>(W_o1);
    init_k<<<64, 256>>>(enc_h0, dec_h0);

    // embed = relu(inputs @ W_e^T + b_e)
    gemm_k<<<dim3(512, 2), 256>>>(inputs, W_e, b_e, (float*)p_embed, 32768, 128, 1024, 1);
    // a1 = relu(embed @ W_a1^T + b_a1)
    gemm_k<<<dim3(512, 2), 256>>>((const float*)p_embed, W_a1, b_a1, (float*)p_a1v, 32768, 128, 128, 1);
    // attention logits + softmax over time
    logits_k<<<128, 256>>>(W_a2, b_a2);
    softmax_k<<<dim3(32, 3), 256>>>();
    // x_proj = embed @ Wih_e^T + (bih_e + bhh_e)
    gemm_k<<<dim3(512, 32), 256>>>((const float*)p_embed, Wih_e, (const float*)p_be, (float*)p_xp, 32768, 2048, 128, 0);
    transp_k<<<dim3(1024, 32), 256>>>();
    // encoder LSTM (persistent, 1 split-phase barrier per step)
    enc_k<<<128, 256, 98304>>>(Whh_e, enc_c0);
    // context = local attention over encoder outputs (with length mask)
    conv_k<<<dim3(1024, 8), 256>>>(lengths);
    // decoder LSTM + output MLP (persistent, 1 barrier + p-flag per step)
    dec_k<<<128, 256, 196608>>>(Wih_d, Whh_d, bih_d, bhh_d, dec_c0,
                                b_o1, W_o2, b_o2, mask, out);
}